// round 1
// baseline (speedup 1.0000x reference)
#include <cuda_runtime.h>
#include <math.h>

#define BATCH 256
#define NPOS 4
#define NNEG 1024
#define DIM 512
#define NSPLIT 4
#define NPS (NNEG / NSPLIT)   // 256 negatives per split-block
#define TEMP_INV 10.0f        // 1 / 0.1
#define POSW 0.3f
#define EPSV 1e-8f

// Scratch (device globals; no allocation allowed)
__device__ float g_pm[BATCH * NSPLIT];            // partial max of l = sim/T over negs
__device__ float g_pz[BATCH * NSPLIT];            // partial sum exp(l - m)
__device__ int   g_pc[BATCH * NSPLIT * NPOS];     // partial counts: #neg sim > pos sim[p]
__device__ float g_possim[BATCH * NPOS];          // raw pos cosine sims

__device__ __forceinline__ float dot16(const float4& x0, const float4& x1,
                                       const float4& x2, const float4& x3,
                                       const float4& y0, const float4& y1,
                                       const float4& y2, const float4& y3) {
    float d = x0.x * y0.x;
    d = fmaf(x0.y, y0.y, d); d = fmaf(x0.z, y0.z, d); d = fmaf(x0.w, y0.w, d);
    d = fmaf(x1.x, y1.x, d); d = fmaf(x1.y, y1.y, d); d = fmaf(x1.z, y1.z, d);
    d = fmaf(x1.w, y1.w, d);
    d = fmaf(x2.x, y2.x, d); d = fmaf(x2.y, y2.y, d); d = fmaf(x2.z, y2.z, d);
    d = fmaf(x2.w, y2.w, d);
    d = fmaf(x3.x, y3.x, d); d = fmaf(x3.y, y3.y, d); d = fmaf(x3.z, y3.z, d);
    d = fmaf(x3.w, y3.w, d);
    return d;
}

__global__ __launch_bounds__(256)
void rrl_pass1(const float* __restrict__ anchor,
               const float* __restrict__ positives,
               const float* __restrict__ negatives) {
    const int b     = blockIdx.x;
    const int split = blockIdx.y;
    const int tid   = threadIdx.x;
    const int lane  = tid & 31;
    const int warp  = tid >> 5;

    __shared__ float s_anorm;
    __shared__ float s_psim[NPOS];
    __shared__ float s_m[8];
    __shared__ float s_z[8];
    __shared__ int   s_c[8][NPOS];

    // --- anchor slice into registers: lane covers float4 chunks lane + k*32 ---
    const float4* a4 = (const float4*)(anchor + (size_t)b * DIM);
    const float4 a0 = a4[lane], a1 = a4[lane + 32], a2 = a4[lane + 64], a3 = a4[lane + 96];

    // ||a||^2 (every warp has the data; warp 0 publishes)
    float asq = dot16(a0, a1, a2, a3, a0, a1, a2, a3);
    #pragma unroll
    for (int o = 16; o; o >>= 1) asq += __shfl_xor_sync(0xffffffffu, asq, o);
    if (warp == 0 && lane == 0) s_anorm = sqrtf(asq);
    __syncthreads();
    const float anorm = s_anorm;

    // --- positive sims: warps 0..3, one positive each ---
    if (warp < NPOS) {
        const float4* p4 = (const float4*)(positives + ((size_t)b * NPOS + warp) * DIM);
        const float4 p0 = p4[lane], p1 = p4[lane + 32], p2 = p4[lane + 64], p3 = p4[lane + 96];
        float pd = dot16(p0, p1, p2, p3, a0, a1, a2, a3);
        float pq = dot16(p0, p1, p2, p3, p0, p1, p2, p3);
        #pragma unroll
        for (int o = 16; o; o >>= 1) {
            pd += __shfl_xor_sync(0xffffffffu, pd, o);
            pq += __shfl_xor_sync(0xffffffffu, pq, o);
        }
        if (lane == 0) {
            float sim = pd / fmaxf(anorm * sqrtf(pq), EPSV);
            s_psim[warp] = sim;
            if (split == 0) g_possim[b * NPOS + warp] = sim;
        }
    }
    __syncthreads();
    const float p0s = s_psim[0], p1s = s_psim[1], p2s = s_psim[2], p3s = s_psim[3];

    // --- stream this split's negatives: warp-per-negative ---
    const float4* nbase = (const float4*)(negatives + ((size_t)b * NNEG + (size_t)split * NPS) * DIM);
    float m = -INFINITY, z = 0.0f;
    int c0 = 0, c1 = 0, c2 = 0, c3 = 0;

    for (int j = warp; j < NPS; j += 8) {
        const float4* n4 = nbase + (size_t)j * (DIM / 4);
        const float4 v0 = n4[lane], v1 = n4[lane + 32], v2 = n4[lane + 64], v3 = n4[lane + 96];
        float d  = dot16(v0, v1, v2, v3, a0, a1, a2, a3);
        float sq = dot16(v0, v1, v2, v3, v0, v1, v2, v3);
        #pragma unroll
        for (int o = 16; o; o >>= 1) {
            d  += __shfl_xor_sync(0xffffffffu, d, o);
            sq += __shfl_xor_sync(0xffffffffu, sq, o);
        }
        // every lane holds identical reduced values -> identical state updates
        const float sim = d / fmaxf(anorm * sqrtf(sq), EPSV);
        const float l   = sim * TEMP_INV;
        const float nm  = fmaxf(m, l);
        z = z * __expf(m - nm) + __expf(l - nm);
        m = nm;
        c0 += (sim > p0s); c1 += (sim > p1s); c2 += (sim > p2s); c3 += (sim > p3s);
    }

    if (lane == 0) {
        s_m[warp] = m; s_z[warp] = z;
        s_c[warp][0] = c0; s_c[warp][1] = c1; s_c[warp][2] = c2; s_c[warp][3] = c3;
    }
    __syncthreads();

    // --- combine 8 warps (fixed order, deterministic), write partials ---
    if (tid == 0) {
        float M = s_m[0], Z = s_z[0];
        int t0 = s_c[0][0], t1 = s_c[0][1], t2 = s_c[0][2], t3 = s_c[0][3];
        #pragma unroll
        for (int w = 1; w < 8; w++) {
            const float nm = fmaxf(M, s_m[w]);
            Z = Z * __expf(M - nm) + s_z[w] * __expf(s_m[w] - nm);
            M = nm;
            t0 += s_c[w][0]; t1 += s_c[w][1]; t2 += s_c[w][2]; t3 += s_c[w][3];
        }
        const int idx = b * NSPLIT + split;
        g_pm[idx] = M;
        g_pz[idx] = Z;
        g_pc[idx * NPOS + 0] = t0;
        g_pc[idx * NPOS + 1] = t1;
        g_pc[idx * NPOS + 2] = t2;
        g_pc[idx * NPOS + 3] = t3;
    }
}

__global__ __launch_bounds__(256)
void rrl_pass2(float* __restrict__ out) {
    const int b = threadIdx.x;  // one thread per batch row (BATCH == 256)

    __shared__ float s_err[256];
    __shared__ float s_pos[256];

    float ps[NPOS], lp[NPOS];
    #pragma unroll
    for (int p = 0; p < NPOS; p++) {
        ps[p] = g_possim[b * NPOS + p];
        lp[p] = ps[p] * TEMP_INV;
    }

    // global max of l over all 1028 sims
    float M = fmaxf(fmaxf(lp[0], lp[1]), fmaxf(lp[2], lp[3]));
    #pragma unroll
    for (int s = 0; s < NSPLIT; s++) M = fmaxf(M, g_pm[b * NSPLIT + s]);

    // denominator
    float Z = 0.0f;
    #pragma unroll
    for (int s = 0; s < NSPLIT; s++)
        Z += g_pz[b * NSPLIT + s] * __expf(g_pm[b * NSPLIT + s] - M);
    #pragma unroll
    for (int p = 0; p < NPOS; p++) Z += __expf(lp[p] - M);

    // expected reciprocal rank
    float err = 0.0f, psum = 0.0f;
    #pragma unroll
    for (int p = 0; p < NPOS; p++) {
        int cnt = 0;
        #pragma unroll
        for (int s = 0; s < NSPLIT; s++) cnt += g_pc[(b * NSPLIT + s) * NPOS + p];
        #pragma unroll
        for (int q = 0; q < NPOS; q++) {
            // stable-sort tie semantics: earlier index wins on exact tie
            cnt += (ps[q] > ps[p]) || ((ps[q] == ps[p]) && (q < p));
        }
        const float prob = __expf(lp[p] - M) / Z;
        err += prob * (1.0f / (float)(cnt + 1));
        psum += ps[p];
    }

    s_err[b] = err;
    s_pos[b] = psum;
    __syncthreads();

    // deterministic tree reduction
    for (int step = 128; step > 0; step >>= 1) {
        if (b < step) {
            s_err[b] += s_err[b + step];
            s_pos[b] += s_pos[b + step];
        }
        __syncthreads();
    }
    if (b == 0) {
        const float loss = -(s_err[0] / (float)BATCH)
                         + POSW * (1.0f - s_pos[0] / (float)(BATCH * NPOS));
        out[0] = loss;
    }
}

extern "C" void kernel_launch(void* const* d_in, const int* in_sizes, int n_in,
                              void* d_out, int out_size) {
    const float* anchor    = (const float*)d_in[0];
    const float* positives = (const float*)d_in[1];
    const float* negatives = (const float*)d_in[2];
    float* out = (float*)d_out;

    dim3 grid(BATCH, NSPLIT);
    rrl_pass1<<<grid, 256>>>(anchor, positives, negatives);
    rrl_pass2<<<1, 256>>>(out);
}

// round 2
// speedup vs baseline: 1.1489x; 1.1489x over previous
#include <cuda_runtime.h>
#include <math.h>

#define BATCH 256
#define NPOS 4
#define NNEG 1024
#define DIM 512
#define NSPLIT 8
#define NPS (NNEG / NSPLIT)   // 128 negatives per split-block
#define TEMP_INV 10.0f        // 1 / 0.1
#define POSW 0.3f
#define EPSV 1e-8f
#define NBLOCKS (BATCH * NSPLIT)

// Scratch (device globals; no allocation allowed)
__device__ float g_pz[BATCH * NSPLIT];            // partial sum exp(10*sim) over negs
__device__ int   g_pc[BATCH * NSPLIT * NPOS];     // partial counts: #neg sim > pos sim[p]
__device__ float g_possim[BATCH * NPOS];          // raw pos cosine sims
__device__ int   g_arrive = 0;                    // grid arrival counter (reset each run)

__device__ __forceinline__ float dot16(const float4& x0, const float4& x1,
                                       const float4& x2, const float4& x3,
                                       const float4& y0, const float4& y1,
                                       const float4& y2, const float4& y3) {
    float d = x0.x * y0.x;
    d = fmaf(x0.y, y0.y, d); d = fmaf(x0.z, y0.z, d); d = fmaf(x0.w, y0.w, d);
    d = fmaf(x1.x, y1.x, d); d = fmaf(x1.y, y1.y, d); d = fmaf(x1.z, y1.z, d);
    d = fmaf(x1.w, y1.w, d);
    d = fmaf(x2.x, y2.x, d); d = fmaf(x2.y, y2.y, d); d = fmaf(x2.z, y2.z, d);
    d = fmaf(x2.w, y2.w, d);
    d = fmaf(x3.x, y3.x, d); d = fmaf(x3.y, y3.y, d); d = fmaf(x3.z, y3.z, d);
    d = fmaf(x3.w, y3.w, d);
    return d;
}

__global__ __launch_bounds__(256)
void rrl_fused(const float* __restrict__ anchor,
               const float* __restrict__ positives,
               const float* __restrict__ negatives,
               float* __restrict__ out) {
    const int b     = blockIdx.x & (BATCH - 1);
    const int split = blockIdx.x >> 8;           // blockIdx.x / BATCH
    const int tid   = threadIdx.x;
    const int lane  = tid & 31;
    const int warp  = tid >> 5;

    __shared__ float s_anorm;
    __shared__ float s_psim[NPOS];
    __shared__ float s_z[8];
    __shared__ int   s_c[8][NPOS];
    __shared__ int   s_last;

    // --- anchor slice into registers: lane covers float4 chunks lane + k*32 ---
    const float4* a4 = (const float4*)(anchor + (size_t)b * DIM);
    const float4 a0 = a4[lane], a1 = a4[lane + 32], a2 = a4[lane + 64], a3 = a4[lane + 96];

    // ||a|| (warp 0 publishes)
    float asq = dot16(a0, a1, a2, a3, a0, a1, a2, a3);
    #pragma unroll
    for (int o = 16; o; o >>= 1) asq += __shfl_xor_sync(0xffffffffu, asq, o);
    if (tid == 0) s_anorm = sqrtf(asq);
    __syncthreads();
    const float anorm = s_anorm;

    // --- positive sims: warps 0..3, one positive each ---
    if (warp < NPOS) {
        const float4* p4 = (const float4*)(positives + ((size_t)b * NPOS + warp) * DIM);
        const float4 p0 = p4[lane], p1 = p4[lane + 32], p2 = p4[lane + 64], p3 = p4[lane + 96];
        float pd = dot16(p0, p1, p2, p3, a0, a1, a2, a3);
        float pq = dot16(p0, p1, p2, p3, p0, p1, p2, p3);
        #pragma unroll
        for (int o = 16; o; o >>= 1) {
            pd += __shfl_xor_sync(0xffffffffu, pd, o);
            pq += __shfl_xor_sync(0xffffffffu, pq, o);
        }
        if (lane == 0) {
            float sim = pd / fmaxf(anorm * sqrtf(pq), EPSV);
            s_psim[warp] = sim;
            if (split == 0) g_possim[b * NPOS + warp] = sim;
        }
    }
    __syncthreads();
    const float p0s = s_psim[0], p1s = s_psim[1], p2s = s_psim[2], p3s = s_psim[3];

    // --- stream this split's negatives: warp-per-negative, 2x unroll ---
    const float4* nbase = (const float4*)(negatives + ((size_t)b * NNEG + (size_t)split * NPS) * DIM);
    float z = 0.0f;
    int c0 = 0, c1 = 0, c2 = 0, c3 = 0;

    #pragma unroll 2
    for (int j = warp; j < NPS; j += 16) {
        const float4* na = nbase + (size_t)j * (DIM / 4);
        const float4* nb = nbase + (size_t)(j + 8) * (DIM / 4);
        const float4 u0 = na[lane], u1 = na[lane + 32], u2 = na[lane + 64], u3 = na[lane + 96];
        const float4 v0 = nb[lane], v1 = nb[lane + 32], v2 = nb[lane + 64], v3 = nb[lane + 96];

        float da  = dot16(u0, u1, u2, u3, a0, a1, a2, a3);
        float sa  = dot16(u0, u1, u2, u3, u0, u1, u2, u3);
        float db  = dot16(v0, v1, v2, v3, a0, a1, a2, a3);
        float sb  = dot16(v0, v1, v2, v3, v0, v1, v2, v3);
        #pragma unroll
        for (int o = 16; o; o >>= 1) {
            da += __shfl_xor_sync(0xffffffffu, da, o);
            sa += __shfl_xor_sync(0xffffffffu, sa, o);
            db += __shfl_xor_sync(0xffffffffu, db, o);
            sb += __shfl_xor_sync(0xffffffffu, sb, o);
        }
        // every lane holds identical reduced values -> identical state updates
        const float sima = da / fmaxf(anorm * sqrtf(sa), EPSV);
        const float simb = db / fmaxf(anorm * sqrtf(sb), EPSV);
        z += __expf(sima * TEMP_INV) + __expf(simb * TEMP_INV);
        c0 += (sima > p0s) + (simb > p0s);
        c1 += (sima > p1s) + (simb > p1s);
        c2 += (sima > p2s) + (simb > p2s);
        c3 += (sima > p3s) + (simb > p3s);
    }

    if (lane == 0) {
        s_z[warp] = z;
        s_c[warp][0] = c0; s_c[warp][1] = c1; s_c[warp][2] = c2; s_c[warp][3] = c3;
    }
    __syncthreads();

    // --- combine 8 warps (fixed order, deterministic), write partials ---
    if (tid == 0) {
        float Z = 0.0f;
        int t0 = 0, t1 = 0, t2 = 0, t3 = 0;
        #pragma unroll
        for (int w = 0; w < 8; w++) {
            Z += s_z[w];
            t0 += s_c[w][0]; t1 += s_c[w][1]; t2 += s_c[w][2]; t3 += s_c[w][3];
        }
        const int idx = b * NSPLIT + split;
        g_pz[idx] = Z;
        g_pc[idx * NPOS + 0] = t0;
        g_pc[idx * NPOS + 1] = t1;
        g_pc[idx * NPOS + 2] = t2;
        g_pc[idx * NPOS + 3] = t3;
        __threadfence();
        s_last = (atomicAdd(&g_arrive, 1) == NBLOCKS - 1);
    }
    __syncthreads();
    if (!s_last) return;

    // ============ final block: full reduction (thread r = batch row) ============
    {
        const int r = tid;  // 0..255 == BATCH
        __shared__ float s_err[256];
        __shared__ float s_pos[256];

        float ps[NPOS], ex[NPOS];
        float Z = 0.0f;
        #pragma unroll
        for (int p = 0; p < NPOS; p++) {
            ps[p] = g_possim[r * NPOS + p];
            ex[p] = __expf(ps[p] * TEMP_INV);
            Z += ex[p];
        }
        #pragma unroll
        for (int s = 0; s < NSPLIT; s++) Z += g_pz[r * NSPLIT + s];

        float err = 0.0f, psum = 0.0f;
        #pragma unroll
        for (int p = 0; p < NPOS; p++) {
            int cnt = 0;
            #pragma unroll
            for (int s = 0; s < NSPLIT; s++) cnt += g_pc[(r * NSPLIT + s) * NPOS + p];
            #pragma unroll
            for (int q = 0; q < NPOS; q++) {
                // stable-sort tie semantics: earlier index wins on exact tie
                cnt += (ps[q] > ps[p]) || ((ps[q] == ps[p]) && (q < p));
            }
            err += (ex[p] / Z) * (1.0f / (float)(cnt + 1));
            psum += ps[p];
        }

        s_err[r] = err;
        s_pos[r] = psum;
        __syncthreads();
        for (int step = 128; step > 0; step >>= 1) {
            if (r < step) {
                s_err[r] += s_err[r + step];
                s_pos[r] += s_pos[r + step];
            }
            __syncthreads();
        }
        if (r == 0) {
            out[0] = -(s_err[0] / (float)BATCH)
                     + POSW * (1.0f - s_pos[0] / (float)(BATCH * NPOS));
            g_arrive = 0;  // reset for next graph replay
        }
    }
}

extern "C" void kernel_launch(void* const* d_in, const int* in_sizes, int n_in,
                              void* d_out, int out_size) {
    const float* anchor    = (const float*)d_in[0];
    const float* positives = (const float*)d_in[1];
    const float* negatives = (const float*)d_in[2];
    float* out = (float*)d_out;

    rrl_fused<<<NBLOCKS, 256>>>(anchor, positives, negatives, out);
}

// round 3
// speedup vs baseline: 1.2523x; 1.0900x over previous
#include <cuda_runtime.h>
#include <math.h>

#define BATCH 256
#define NPOS 4
#define NNEG 1024
#define DIM 512
#define TEMP_INV 10.0f        // 1 / 0.1
#define POSW 0.3f
#define EPSV 1e-8f
#define GRID 888              // 148 SMs * 6 CTAs -> one resident wave
#define TOTAL_ROWS (BATCH * NNEG)

// Scratch (device globals, zero-initialized at load; reset by last CTA each run)
__device__ float g_pz[BATCH];             // sum over negs of exp(10*sim)
__device__ int   g_pc[BATCH * NPOS];      // #neg sim > pos sim[p]
__device__ float g_possim[BATCH * NPOS];  // raw pos cosine sims
__device__ int   g_arrive = 0;            // arrival counter

__device__ __forceinline__ float dot16t(const float4& x0, const float4& x1,
                                        const float4& x2, const float4& x3,
                                        const float4& y0, const float4& y1,
                                        const float4& y2, const float4& y3) {
    float p0 = x0.x * y0.x; p0 = fmaf(x0.y, y0.y, p0); p0 = fmaf(x0.z, y0.z, p0); p0 = fmaf(x0.w, y0.w, p0);
    float p1 = x1.x * y1.x; p1 = fmaf(x1.y, y1.y, p1); p1 = fmaf(x1.z, y1.z, p1); p1 = fmaf(x1.w, y1.w, p1);
    float p2 = x2.x * y2.x; p2 = fmaf(x2.y, y2.y, p2); p2 = fmaf(x2.z, y2.z, p2); p2 = fmaf(x2.w, y2.w, p2);
    float p3 = x3.x * y3.x; p3 = fmaf(x3.y, y3.y, p3); p3 = fmaf(x3.z, y3.z, p3); p3 = fmaf(x3.w, y3.w, p3);
    return (p0 + p1) + (p2 + p3);
}

__global__ __launch_bounds__(128)
void rrl_persist(const float* __restrict__ anchor,
                 const float* __restrict__ positives,
                 const float* __restrict__ negatives,
                 float* __restrict__ out) {
    const int tid  = threadIdx.x;
    const int lane = tid & 31;
    const int warp = tid >> 5;
    const int cta  = blockIdx.x;

    // flat row range for this CTA (equal +-1)
    int cnt = TOTAL_ROWS / GRID;                  // 295
    const int rem = TOTAL_ROWS - cnt * GRID;      // 184
    int start = cta * cnt + min(cta, rem);
    if (cta < rem) cnt++;
    const int end = start + cnt;

    __shared__ float s_psim[NPOS];
    __shared__ int   s_last;

    int row = start;
    while (row < end) {
        const int b    = row >> 10;               // row / NNEG
        const int bend = min(end, (b + 1) << 10);
        __syncthreads();                          // protect s_psim reuse

        // --- anchor slice (per-warp copy): lane covers float4 chunks lane + k*32 ---
        const float4* a4 = (const float4*)(anchor + (size_t)b * DIM);
        const float4 a0 = a4[lane], a1 = a4[lane + 32], a2 = a4[lane + 64], a3 = a4[lane + 96];
        float asq = dot16t(a0, a1, a2, a3, a0, a1, a2, a3);
        #pragma unroll
        for (int o = 16; o; o >>= 1) asq += __shfl_xor_sync(0xffffffffu, asq, o);
        const float inva = rsqrtf(asq);           // 1 / ||a||

        // --- positive sims: warp w computes positive w, share via smem ---
        {
            const float4* p4 = (const float4*)(positives + ((size_t)b * NPOS + warp) * DIM);
            const float4 p0 = p4[lane], p1 = p4[lane + 32], p2 = p4[lane + 64], p3 = p4[lane + 96];
            float pd = dot16t(p0, p1, p2, p3, a0, a1, a2, a3);
            float pq = dot16t(p0, p1, p2, p3, p0, p1, p2, p3);
            #pragma unroll
            for (int o = 16; o; o >>= 1) {
                pd += __shfl_xor_sync(0xffffffffu, pd, o);
                pq += __shfl_xor_sync(0xffffffffu, pq, o);
            }
            if (lane == 0) {
                const float sim = pd * rsqrtf(pq) * inva;
                s_psim[warp] = sim;
                g_possim[b * NPOS + warp] = sim;  // duplicate identical writes: benign
            }
        }
        __syncthreads();
        const float p0s = s_psim[0], p1s = s_psim[1], p2s = s_psim[2], p3s = s_psim[3];

        // --- stream rows [row, bend): warp-per-row, 2x pairing for MLP ---
        const float4* nbase = (const float4*)negatives;
        float z = 0.0f;
        int c0 = 0, c1 = 0, c2 = 0, c3 = 0;

        int j = row + warp;
        for (; j + 4 < bend; j += 8) {
            const float4* na = nbase + (size_t)j * (DIM / 4);
            const float4* nb = nbase + (size_t)(j + 4) * (DIM / 4);
            const float4 u0 = __ldcs(na + lane), u1 = __ldcs(na + lane + 32),
                         u2 = __ldcs(na + lane + 64), u3 = __ldcs(na + lane + 96);
            const float4 v0 = __ldcs(nb + lane), v1 = __ldcs(nb + lane + 32),
                         v2 = __ldcs(nb + lane + 64), v3 = __ldcs(nb + lane + 96);

            float da = dot16t(u0, u1, u2, u3, a0, a1, a2, a3);
            float sa = dot16t(u0, u1, u2, u3, u0, u1, u2, u3);
            float db = dot16t(v0, v1, v2, v3, a0, a1, a2, a3);
            float sb = dot16t(v0, v1, v2, v3, v0, v1, v2, v3);
            #pragma unroll
            for (int o = 16; o; o >>= 1) {
                da += __shfl_xor_sync(0xffffffffu, da, o);
                sa += __shfl_xor_sync(0xffffffffu, sa, o);
                db += __shfl_xor_sync(0xffffffffu, db, o);
                sb += __shfl_xor_sync(0xffffffffu, sb, o);
            }
            const float sima = da * rsqrtf(sa) * inva;
            const float simb = db * rsqrtf(sb) * inva;
            z += __expf(sima * TEMP_INV) + __expf(simb * TEMP_INV);
            c0 += (sima > p0s) + (simb > p0s);
            c1 += (sima > p1s) + (simb > p1s);
            c2 += (sima > p2s) + (simb > p2s);
            c3 += (sima > p3s) + (simb > p3s);
        }
        if (j < bend) {
            const float4* na = nbase + (size_t)j * (DIM / 4);
            const float4 u0 = __ldcs(na + lane), u1 = __ldcs(na + lane + 32),
                         u2 = __ldcs(na + lane + 64), u3 = __ldcs(na + lane + 96);
            float da = dot16t(u0, u1, u2, u3, a0, a1, a2, a3);
            float sa = dot16t(u0, u1, u2, u3, u0, u1, u2, u3);
            #pragma unroll
            for (int o = 16; o; o >>= 1) {
                da += __shfl_xor_sync(0xffffffffu, da, o);
                sa += __shfl_xor_sync(0xffffffffu, sa, o);
            }
            const float sima = da * rsqrtf(sa) * inva;
            z += __expf(sima * TEMP_INV);
            c0 += (sima > p0s); c1 += (sima > p1s); c2 += (sima > p2s); c3 += (sima > p3s);
        }

        // lanes hold identical reduced state; lane 0 merges to global
        if (lane == 0) {
            atomicAdd(&g_pz[b], z);
            atomicAdd(&g_pc[b * NPOS + 0], c0);
            atomicAdd(&g_pc[b * NPOS + 1], c1);
            atomicAdd(&g_pc[b * NPOS + 2], c2);
            atomicAdd(&g_pc[b * NPOS + 3], c3);
        }
        row = bend;
    }

    __threadfence();
    __syncthreads();
    if (tid == 0) s_last = (atomicAdd(&g_arrive, 1) == GRID - 1);
    __syncthreads();
    if (!s_last) return;

    // ============ last CTA: final math. 128 threads, 2 batch rows each ============
    {
        __shared__ float s_err[128];
        __shared__ float s_pos[128];

        float err = 0.0f, psum = 0.0f;
        #pragma unroll
        for (int h = 0; h < 2; h++) {
            const int r = tid + h * 128;
            float ps[NPOS], ex[NPOS];
            float Z = g_pz[r];
            #pragma unroll
            for (int p = 0; p < NPOS; p++) {
                ps[p] = g_possim[r * NPOS + p];
                ex[p] = __expf(ps[p] * TEMP_INV);
                Z += ex[p];
            }
            #pragma unroll
            for (int p = 0; p < NPOS; p++) {
                int cntp = g_pc[r * NPOS + p];
                #pragma unroll
                for (int q = 0; q < NPOS; q++)
                    cntp += (ps[q] > ps[p]) || ((ps[q] == ps[p]) && (q < p));  // stable ties
                err += (ex[p] / Z) * (1.0f / (float)(cntp + 1));
                psum += ps[p];
            }
        }
        s_err[tid] = err;
        s_pos[tid] = psum;
        __syncthreads();
        for (int step = 64; step > 0; step >>= 1) {
            if (tid < step) {
                s_err[tid] += s_err[tid + step];
                s_pos[tid] += s_pos[tid + step];
            }
            __syncthreads();
        }

        // reset scratch for next graph replay (after all reads above)
        #pragma unroll
        for (int h = 0; h < 2; h++) {
            const int r = tid + h * 128;
            g_pz[r] = 0.0f;
            #pragma unroll
            for (int p = 0; p < NPOS; p++) g_pc[r * NPOS + p] = 0;
        }
        if (tid == 0) {
            out[0] = -(s_err[0] / (float)BATCH)
                     + POSW * (1.0f - s_pos[0] / (float)(BATCH * NPOS));
            g_arrive = 0;
        }
    }
}

extern "C" void kernel_launch(void* const* d_in, const int* in_sizes, int n_in,
                              void* d_out, int out_size) {
    const float* anchor    = (const float*)d_in[0];
    const float* positives = (const float*)d_in[1];
    const float* negatives = (const float*)d_in[2];
    float* out = (float*)d_out;

    rrl_persist<<<GRID, 128>>>(anchor, positives, negatives, out);
}

// round 4
// speedup vs baseline: 1.2730x; 1.0165x over previous
#include <cuda_runtime.h>
#include <math.h>

#define BATCH 256
#define NPOS 4
#define NNEG 1024
#define DIM 512
#define TEMP_INV 10.0f        // 1 / 0.1
#define POSW 0.3f
#define EPSV 1e-8f
#define GRID 1184             // 148 SMs * 8 CTAs -> one resident wave
#define TOTAL_ROWS (BATCH * NNEG)

// Scratch (device globals, zero-initialized at load; reset by last CTA each run)
__device__ float g_pz[BATCH];             // sum over negs of exp(10*sim)
__device__ int   g_pc[BATCH * NPOS];      // #neg sim > pos sim[p]
__device__ float g_possim[BATCH * NPOS];  // raw pos cosine sims
__device__ int   g_arrive = 0;            // arrival counter

__device__ __forceinline__ float dot16t(const float4& x0, const float4& x1,
                                        const float4& x2, const float4& x3,
                                        const float4& y0, const float4& y1,
                                        const float4& y2, const float4& y3) {
    float p0 = x0.x * y0.x; p0 = fmaf(x0.y, y0.y, p0); p0 = fmaf(x0.z, y0.z, p0); p0 = fmaf(x0.w, y0.w, p0);
    float p1 = x1.x * y1.x; p1 = fmaf(x1.y, y1.y, p1); p1 = fmaf(x1.z, y1.z, p1); p1 = fmaf(x1.w, y1.w, p1);
    float p2 = x2.x * y2.x; p2 = fmaf(x2.y, y2.y, p2); p2 = fmaf(x2.z, y2.z, p2); p2 = fmaf(x2.w, y2.w, p2);
    float p3 = x3.x * y3.x; p3 = fmaf(x3.y, y3.y, p3); p3 = fmaf(x3.z, y3.z, p3); p3 = fmaf(x3.w, y3.w, p3);
    return (p0 + p1) + (p2 + p3);
}

__global__ __launch_bounds__(128, 8)
void rrl_persist(const float* __restrict__ anchor,
                 const float* __restrict__ positives,
                 const float* __restrict__ negatives,
                 float* __restrict__ out) {
    const int tid  = threadIdx.x;
    const int lane = tid & 31;
    const int warp = tid >> 5;
    const int cta  = blockIdx.x;

    // flat row range for this CTA (equal +-1)
    int cnt = TOTAL_ROWS / GRID;                  // 221
    const int rem = TOTAL_ROWS - cnt * GRID;      // 480
    int start = cta * cnt + min(cta, rem);
    if (cta < rem) cnt++;
    const int end = start + cnt;

    __shared__ float s_psim[NPOS];
    __shared__ int   s_last;

    int row = start;
    while (row < end) {
        const int b    = row >> 10;               // row / NNEG
        const int bend = min(end, (b + 1) << 10);
        __syncthreads();                          // protect s_psim reuse

        // --- anchor slice (per-warp copy): lane covers float4 chunks lane + k*32 ---
        const float4* a4 = (const float4*)(anchor + (size_t)b * DIM);
        const float4 a0 = a4[lane], a1 = a4[lane + 32], a2 = a4[lane + 64], a3 = a4[lane + 96];
        float asq = dot16t(a0, a1, a2, a3, a0, a1, a2, a3);
        #pragma unroll
        for (int o = 16; o; o >>= 1) asq += __shfl_xor_sync(0xffffffffu, asq, o);
        const float inva = rsqrtf(asq);           // 1 / ||a||

        // --- positive sims: warp w computes positive w, share via smem ---
        {
            const float4* p4 = (const float4*)(positives + ((size_t)b * NPOS + warp) * DIM);
            const float4 p0 = p4[lane], p1 = p4[lane + 32], p2 = p4[lane + 64], p3 = p4[lane + 96];
            float pd = dot16t(p0, p1, p2, p3, a0, a1, a2, a3);
            float pq = dot16t(p0, p1, p2, p3, p0, p1, p2, p3);
            #pragma unroll
            for (int o = 16; o; o >>= 1) {
                pd += __shfl_xor_sync(0xffffffffu, pd, o);
                pq += __shfl_xor_sync(0xffffffffu, pq, o);
            }
            if (lane == 0) {
                const float sim = pd * rsqrtf(pq) * inva;
                s_psim[warp] = sim;
                g_possim[b * NPOS + warp] = sim;  // duplicate identical writes: benign
            }
        }
        __syncthreads();
        const float p0s = s_psim[0], p1s = s_psim[1], p2s = s_psim[2], p3s = s_psim[3];

        // --- stream rows [row, bend): warp-per-row, 2x pairing for MLP ---
        const float4* nbase = (const float4*)negatives;
        float z = 0.0f;
        int c0 = 0, c1 = 0, c2 = 0, c3 = 0;

        int j = row + warp;
        for (; j + 4 < bend; j += 8) {
            const float4* na = nbase + (size_t)j * (DIM / 4);
            const float4* nb = nbase + (size_t)(j + 4) * (DIM / 4);
            const float4 u0 = __ldcs(na + lane), u1 = __ldcs(na + lane + 32),
                         u2 = __ldcs(na + lane + 64), u3 = __ldcs(na + lane + 96);
            const float4 v0 = __ldcs(nb + lane), v1 = __ldcs(nb + lane + 32),
                         v2 = __ldcs(nb + lane + 64), v3 = __ldcs(nb + lane + 96);

            float da = dot16t(u0, u1, u2, u3, a0, a1, a2, a3);
            float sa = dot16t(u0, u1, u2, u3, u0, u1, u2, u3);
            float db = dot16t(v0, v1, v2, v3, a0, a1, a2, a3);
            float sb = dot16t(v0, v1, v2, v3, v0, v1, v2, v3);
            #pragma unroll
            for (int o = 16; o; o >>= 1) {
                da += __shfl_xor_sync(0xffffffffu, da, o);
                sa += __shfl_xor_sync(0xffffffffu, sa, o);
                db += __shfl_xor_sync(0xffffffffu, db, o);
                sb += __shfl_xor_sync(0xffffffffu, sb, o);
            }
            const float sima = da * rsqrtf(sa) * inva;
            const float simb = db * rsqrtf(sb) * inva;
            z += __expf(sima * TEMP_INV) + __expf(simb * TEMP_INV);
            c0 += (sima > p0s) + (simb > p0s);
            c1 += (sima > p1s) + (simb > p1s);
            c2 += (sima > p2s) + (simb > p2s);
            c3 += (sima > p3s) + (simb > p3s);
        }
        if (j < bend) {
            const float4* na = nbase + (size_t)j * (DIM / 4);
            const float4 u0 = __ldcs(na + lane), u1 = __ldcs(na + lane + 32),
                         u2 = __ldcs(na + lane + 64), u3 = __ldcs(na + lane + 96);
            float da = dot16t(u0, u1, u2, u3, a0, a1, a2, a3);
            float sa = dot16t(u0, u1, u2, u3, u0, u1, u2, u3);
            #pragma unroll
            for (int o = 16; o; o >>= 1) {
                da += __shfl_xor_sync(0xffffffffu, da, o);
                sa += __shfl_xor_sync(0xffffffffu, sa, o);
            }
            const float sima = da * rsqrtf(sa) * inva;
            z += __expf(sima * TEMP_INV);
            c0 += (sima > p0s); c1 += (sima > p1s); c2 += (sima > p2s); c3 += (sima > p3s);
        }

        // lanes hold identical reduced state; lane 0 merges to global
        if (lane == 0) {
            atomicAdd(&g_pz[b], z);
            atomicAdd(&g_pc[b * NPOS + 0], c0);
            atomicAdd(&g_pc[b * NPOS + 1], c1);
            atomicAdd(&g_pc[b * NPOS + 2], c2);
            atomicAdd(&g_pc[b * NPOS + 3], c3);
        }
        row = bend;
    }

    __threadfence();
    __syncthreads();
    if (tid == 0) s_last = (atomicAdd(&g_arrive, 1) == GRID - 1);
    __syncthreads();
    if (!s_last) return;

    // ============ last CTA: final math. 128 threads, 2 batch rows each ============
    {
        __shared__ float s_err[128];
        __shared__ float s_pos[128];

        float err = 0.0f, psum = 0.0f;
        #pragma unroll
        for (int h = 0; h < 2; h++) {
            const int r = tid + h * 128;
            float ps[NPOS], ex[NPOS];
            float Z = g_pz[r];
            #pragma unroll
            for (int p = 0; p < NPOS; p++) {
                ps[p] = g_possim[r * NPOS + p];
                ex[p] = __expf(ps[p] * TEMP_INV);
                Z += ex[p];
            }
            #pragma unroll
            for (int p = 0; p < NPOS; p++) {
                int cntp = g_pc[r * NPOS + p];
                #pragma unroll
                for (int q = 0; q < NPOS; q++)
                    cntp += (ps[q] > ps[p]) || ((ps[q] == ps[p]) && (q < p));  // stable ties
                err += (ex[p] / Z) * (1.0f / (float)(cntp + 1));
                psum += ps[p];
            }
        }
        s_err[tid] = err;
        s_pos[tid] = psum;
        __syncthreads();
        for (int step = 64; step > 0; step >>= 1) {
            if (tid < step) {
                s_err[tid] += s_err[tid + step];
                s_pos[tid] += s_pos[tid + step];
            }
            __syncthreads();
        }

        // reset scratch for next graph replay (after all reads above)
        #pragma unroll
        for (int h = 0; h < 2; h++) {
            const int r = tid + h * 128;
            g_pz[r] = 0.0f;
            #pragma unroll
            for (int p = 0; p < NPOS; p++) g_pc[r * NPOS + p] = 0;
        }
        if (tid == 0) {
            out[0] = -(s_err[0] / (float)BATCH)
                     + POSW * (1.0f - s_pos[0] / (float)(BATCH * NPOS));
            g_arrive = 0;
        }
    }
}

extern "C" void kernel_launch(void* const* d_in, const int* in_sizes, int n_in,
                              void* d_out, int out_size) {
    const float* anchor    = (const float*)d_in[0];
    const float* positives = (const float*)d_in[1];
    const float* negatives = (const float*)d_in[2];
    float* out = (float*)d_out;

    rrl_persist<<<GRID, 128>>>(anchor, positives, negatives, out);
}